// round 14
// baseline (speedup 1.0000x reference)
#include <cuda_runtime.h>
#include <cuda_fp16.h>
#include <math.h>
#include <stdint.h>

// Problem dims (fixed)
#define BATCH 4
#define SEQ   8192
#define DIM   512
#define HEADS 8
#define MROWS (BATCH*SEQ)

// scan chunking
#define CHUNK  128
#define NCHUNK (SEQ/CHUNK)

// ---------------------------------------------------------------------------
// device scratch (allocation-free rule -> __device__ globals)
// ---------------------------------------------------------------------------
__device__ __half g_xp [(size_t)MROWS*DIM];     // GEMM1 output (fp16)
__device__ __half g_xh [(size_t)MROWS*DIM];     // x as fp16
__device__ __half g_yh [(size_t)MROWS*DIM];     // y as fp16
__device__ __half g_w1 [DIM*DIM];               // W_in  fp16
__device__ __half g_w2 [DIM*DIM];               // W_out fp16
__device__ float  g_e  [(size_t)BATCH*NCHUNK*DIM];  // chunk terminals (partial)
__device__ float  g_cin[(size_t)BATCH*NCHUNK*DIM];
__device__ float  g_alpha[HEADS];

// ---------------------------------------------------------------------------
// helpers
// ---------------------------------------------------------------------------
__device__ __forceinline__ uint32_t s2u(const void* p) {
    uint32_t a;
    asm("{ .reg .u64 t; cvta.to.shared.u64 t, %1; cvt.u32.u64 %0, t; }"
        : "=r"(a) : "l"(p));
    return a;
}

__device__ __forceinline__ void ldsm4(uint32_t& r0, uint32_t& r1,
                                      uint32_t& r2, uint32_t& r3,
                                      uint32_t addr) {
    asm volatile("ldmatrix.sync.aligned.m8n8.x4.shared.b16 {%0,%1,%2,%3}, [%4];"
                 : "=r"(r0), "=r"(r1), "=r"(r2), "=r"(r3) : "r"(addr));
}

__device__ __forceinline__ void mma16816(float* c, const uint32_t* a,
                                         const uint32_t* b) {
    asm volatile(
        "mma.sync.aligned.m16n8k16.row.col.f32.f16.f16.f32 "
        "{%0,%1,%2,%3}, {%4,%5,%6,%7}, {%8,%9}, {%0,%1,%2,%3};"
        : "+f"(c[0]), "+f"(c[1]), "+f"(c[2]), "+f"(c[3])
        : "r"(a[0]), "r"(a[1]), "r"(a[2]), "r"(a[3]), "r"(b[0]), "r"(b[1]));
}

// ---------------------------------------------------------------------------
// weight converts (both) + alpha = sigmoid(alpha_param), one launch
// ---------------------------------------------------------------------------
#define N4W (DIM*DIM/4)
__global__ void __launch_bounds__(256)
convw_kernel(const float* __restrict__ Win, const float* __restrict__ Wout,
             const float* __restrict__ ap) {
    int i = blockIdx.x * 256 + threadIdx.x;
    if (blockIdx.x == 0 && threadIdx.x < HEADS)
        g_alpha[threadIdx.x] = 1.0f / (1.0f + expf(-ap[threadIdx.x]));
    const float* src;
    __half* dst;
    int j;
    if (i < N4W)            { src = Win;  dst = g_w1; j = i; }
    else if (i < 2 * N4W)   { src = Wout; dst = g_w2; j = i - N4W; }
    else return;
    float4 v = ((const float4*)src)[j];
    __half2 h0 = __halves2half2(__float2half_rn(v.x), __float2half_rn(v.y));
    __half2 h1 = __halves2half2(__float2half_rn(v.z), __float2half_rn(v.w));
    ((__half2*)(dst + 4*(size_t)j))[0] = h0;
    ((__half2*)(dst + 4*(size_t)j))[1] = h1;
}

// ---------------------------------------------------------------------------
// x fp32 -> fp16 convert
// ---------------------------------------------------------------------------
__global__ void __launch_bounds__(256)
convx_kernel(const float* __restrict__ src, __half* __restrict__ dst, int n4) {
    int i = blockIdx.x * blockDim.x + threadIdx.x;
    if (i >= n4) return;
    float4 v = ((const float4*)src)[i];
    __half2 h0 = __halves2half2(__float2half_rn(v.x), __float2half_rn(v.y));
    __half2 h1 = __halves2half2(__float2half_rn(v.z), __float2half_rn(v.w));
    ((__half2*)(dst + 4*(size_t)i))[0] = h0;
    ((__half2*)(dst + 4*(size_t)i))[1] = h1;
}

// ---------------------------------------------------------------------------
// fp16 HMMA GEMM (R9-proven): C[m,n] = sum_k A[m,k]*B[n,k] + bias[n]
//   CTA 128x128, BK=64, 256 thr (8 warps 2x4), warp tile 64x32.
//   2-stage cp.async; xor swizzle; ldmatrix.x4; mma.m16n8k16.f16; 2 CTAs/SM.
//   DO_E variant (GEMM1): epilogue additionally emits the scan-chunk terminal
//     e'[chunk,col] = alpha*v[127] - alpha^2 * sum_{t<=126} a^(126-t) v[t]
//   (v = acc+bias, fp32). BM==CHUNK so blockIdx.y IS the chunk index.
//   Coefficients computed with DIRECT powf per term (R13 bug: descending
//   power chain underflowed for a<0.5 and zeroed O(1) coefficients).
// ---------------------------------------------------------------------------
#define BM 128
#define BN 128
#define BK 64
#define KITERS (DIM/BK)     // 8

#define XA_OFF 0
#define BB_OFF 16384
#define STAGE_BYTES 32768
#define SMEM_TOTAL (2*STAGE_BYTES)   // 64 KB

#define TSWZ(row, c16) ((uint32_t)(row) * 128u + 16u * ((uint32_t)(c16) ^ ((uint32_t)(row) & 7u)))

__device__ __forceinline__ void load_stage(uint32_t sbase,
                                           const __half* __restrict__ A,
                                           const __half* __restrict__ B,
                                           int m0, int n0, int k0, int tid) {
#pragma unroll
    for (int q = 0; q < 8; q++) {
        int i = tid + q * 256;
        int mat = i >> 10;            // 0 A, 1 B
        int j = i & 1023;
        int row = j >> 3;
        int c = j & 7;
        const __half* src = (mat ? B + (size_t)(n0 + row) * DIM
                                 : A + (size_t)(m0 + row) * DIM) + k0 + c * 8;
        uint32_t dst = sbase + (mat ? BB_OFF : XA_OFF) + TSWZ(row, c);
        asm volatile("cp.async.cg.shared.global [%0], [%1], 16;"
                     :: "r"(dst), "l"(src));
    }
}

template <typename OutT, bool DO_E>
__global__ void __launch_bounds__(256, 2)
gemm_mma(const __half* __restrict__ A, const __half* __restrict__ B,
         const float* __restrict__ bias, OutT* __restrict__ C) {
    extern __shared__ char smem[];
    uint32_t sb = s2u(smem);

    const int tid  = threadIdx.x;
    const int wid  = tid >> 5;
    const int lane = tid & 31;
    const int wm   = wid >> 2;
    const int wn   = wid & 3;
    const int m0   = blockIdx.y * BM;
    const int n0   = blockIdx.x * BN;

    float acc[4][4][4];
#pragma unroll
    for (int i = 0; i < 4; i++)
#pragma unroll
        for (int j = 0; j < 4; j++)
#pragma unroll
            for (int r = 0; r < 4; r++) acc[i][j][r] = 0.0f;

    const int arow = wm * 64 + (lane & 15);
    const int achk = lane >> 4;
    const int brow = wn * 32 + (lane & 7) + ((lane >> 4) << 3);
    const int bchk = (lane >> 3) & 1;
    const uint32_t sxor = (uint32_t)(lane & 7);

    load_stage(sb, A, B, m0, n0, 0, tid);
    asm volatile("cp.async.commit_group;" ::: "memory");

    for (int it = 0; it < KITERS; it++) {
        if (it + 1 < KITERS) {
            load_stage(sb + ((it + 1) & 1) * STAGE_BYTES,
                       A, B, m0, n0, (it + 1) * BK, tid);
            asm volatile("cp.async.commit_group;" ::: "memory");
            asm volatile("cp.async.wait_group 1;" ::: "memory");
        } else {
            asm volatile("cp.async.wait_group 0;" ::: "memory");
        }
        __syncthreads();

        uint32_t st = sb + (it & 1) * STAGE_BYTES;
#pragma unroll
        for (int ks = 0; ks < BK / 16; ks++) {
            uint32_t av[4][4];
#pragma unroll
            for (int mt = 0; mt < 4; mt++) {
                int row = arow + mt * 16;
                uint32_t co = (uint32_t)(2 * ks + achk) ^ sxor;
                uint32_t off = (uint32_t)row * 128u + co * 16u;
                ldsm4(av[mt][0], av[mt][1], av[mt][2], av[mt][3],
                      st + XA_OFF + off);
            }
            uint32_t bv[4][2];
#pragma unroll
            for (int nt2 = 0; nt2 < 2; nt2++) {
                int row = brow + nt2 * 16;
                uint32_t co = (uint32_t)(2 * ks + bchk) ^ sxor;
                uint32_t off = (uint32_t)row * 128u + co * 16u;
                uint32_t r0, r1, r2, r3;
                ldsm4(r0, r1, r2, r3, st + BB_OFF + off);
                bv[nt2*2][0] = r0; bv[nt2*2][1] = r1;
                bv[nt2*2+1][0] = r2; bv[nt2*2+1][1] = r3;
            }
#pragma unroll
            for (int mt = 0; mt < 4; mt++)
#pragma unroll
                for (int nt = 0; nt < 4; nt++)
                    mma16816(acc[mt][nt], av[mt], bv[nt]);
        }
        __syncthreads();
    }

    // ---- epilogue: C writes (+ optional chunk-terminal reduction) ----
    const int erow = m0 + wm * 64 + (lane >> 2);
    const int ecol = n0 + wn * 32 + 2 * (lane & 3);

    float ecl[8];   // per-thread chunk-terminal partials, one per owned column
    float coef0[4], coef1[4];
    if (DO_E) {
        const float alpha = g_alpha[(n0 + wn * 32) >> 6];  // warp cols = 1 head
        const float a = 1.0f - alpha;
        const float na2 = -alpha * alpha;
        const int rbase = wm * 64 + (lane >> 2);
#pragma unroll
        for (int mt = 0; mt < 4; mt++) {
            int t0 = rbase + mt * 16;      // row (as time index) of c0/c1
            int t1 = t0 + 8;               // row of c2/c3
            // direct powf per coefficient: underflow only when the true
            // coefficient is genuinely negligible (a^k < 1e-38).
            coef0[mt] = na2 * powf(a, (float)(126 - t0));   // t0 <= 119
            coef1[mt] = (t1 == 127) ? alpha
                                    : na2 * powf(a, (float)(126 - t1));
        }
#pragma unroll
        for (int k = 0; k < 8; k++) ecl[k] = 0.0f;
    }

#pragma unroll
    for (int nt = 0; nt < 4; nt++) {
        int col = ecol + nt * 8;
        float b0 = bias[col], b1 = bias[col + 1];
#pragma unroll
        for (int mt = 0; mt < 4; mt++) {
            int row = erow + mt * 16;
            float v00 = acc[mt][nt][0] + b0, v01 = acc[mt][nt][1] + b1;
            float v10 = acc[mt][nt][2] + b0, v11 = acc[mt][nt][3] + b1;
            if (sizeof(OutT) == 4) {
                *(float2*)((float*)C + (size_t)row * DIM + col)
                    = make_float2(v00, v01);
                *(float2*)((float*)C + (size_t)(row + 8) * DIM + col)
                    = make_float2(v10, v11);
            } else {
                *(__half2*)((__half*)C + (size_t)row * DIM + col)
                    = __halves2half2(__float2half_rn(v00), __float2half_rn(v01));
                *(__half2*)((__half*)C + (size_t)(row + 8) * DIM + col)
                    = __halves2half2(__float2half_rn(v10), __float2half_rn(v11));
            }
            if (DO_E) {
                ecl[nt*2+0] += coef0[mt] * v00 + coef1[mt] * v10;
                ecl[nt*2+1] += coef0[mt] * v01 + coef1[mt] * v11;
            }
        }
    }

    if (DO_E) {
        // reduce over the 8 row-owning lanes (lane>>2), keep lane&3 columns
#pragma unroll
        for (int k = 0; k < 8; k++) {
#pragma unroll
            for (int s = 4; s < 32; s <<= 1)
                ecl[k] += __shfl_xor_sync(0xffffffffu, ecl[k], s);
        }
        float* esh = (float*)smem;   // [2][128] partials per wm
        if ((lane >> 2) == 0) {
#pragma unroll
            for (int k = 0; k < 8; k++) {
                int colw = wn * 32 + (k >> 1) * 8 + 2 * (lane & 3) + (k & 1);
                esh[wm * 128 + colw] = ecl[k];
            }
        }
        __syncthreads();
        if (tid < 128) {
            float e = esh[tid] + esh[128 + tid];
            g_e[(size_t)blockIdx.y * DIM + n0 + tid] = e;
        }
    }
}

// ---------------------------------------------------------------------------
// carry: cin[c] = scan state at chunk start. e[c] = e'[c] - alpha*a^127*xp[-1].
// ---------------------------------------------------------------------------
__global__ void __launch_bounds__(512)
carry_kernel(const float* __restrict__ init_state) {
    int d = threadIdx.x;
    int b = blockIdx.x;
    float alpha = g_alpha[d >> 6];
    float a = 1.0f - alpha;
    float aN = powf(a, (float)CHUNK);
    float a127 = powf(a, 127.0f);
    float carry = init_state[d];
#pragma unroll 4
    for (int c = 0; c < NCHUNK; c++) {
        g_cin[((size_t)b * NCHUNK + c) * DIM + d] = carry;
        float prevlast = (c == 0)
            ? init_state[d]
            : __half2float(g_xp[((size_t)b * SEQ + c * CHUNK - 1) * DIM + d]);
        float e = g_e[((size_t)b * NCHUNK + c) * DIM + d]
                  - alpha * a127 * prevlast;
        carry = fmaf(aN, carry, e);
    }
}

// ---------------------------------------------------------------------------
// scan: y[t] = a*y[t-1] + alpha*(xp[t]-xp[t-1]), seeded by cin; emit fp16
// ---------------------------------------------------------------------------
__global__ void scan_kernel(const float* __restrict__ init_state) {
    int d = threadIdx.x;
    int c = blockIdx.x, b = blockIdx.y;
    float alpha = g_alpha[d >> 6];
    float a = 1.0f - alpha;
    int t0 = c * CHUNK;
    size_t off = ((size_t)b * SEQ + t0) * DIM + d;
    const __half* base = g_xp + off;
    __half* y = g_yh + off;
    float prev = (t0 == 0) ? init_state[d] : __half2float(*(base - DIM));
    float l = g_cin[((size_t)b * NCHUNK + c) * DIM + d];
#pragma unroll 4
    for (int t = 0; t < CHUNK; t++) {
        float cur = __half2float(base[(size_t)t * DIM]);
        l = a * l + alpha * (cur - prev);
        prev = cur;
        y[(size_t)t * DIM] = __float2half_rn(l);
    }
}

// ---------------------------------------------------------------------------
// launch
// ---------------------------------------------------------------------------
extern "C" void kernel_launch(void* const* d_in, const int* in_sizes, int n_in,
                              void* d_out, int out_size) {
    const float* x    = (const float*)d_in[0];
    const float* Win  = (const float*)d_in[1];
    const float* bin  = (const float*)d_in[2];
    const float* Wout = (const float*)d_in[3];
    const float* bout = (const float*)d_in[4];
    const float* init = (const float*)d_in[5];
    const float* ap   = (const float*)d_in[6];
    float* out = (float*)d_out;

    cudaFuncSetAttribute((const void*)gemm_mma<__half, true>,
                         cudaFuncAttributeMaxDynamicSharedMemorySize, SMEM_TOTAL);
    cudaFuncSetAttribute((const void*)gemm_mma<float, false>,
                         cudaFuncAttributeMaxDynamicSharedMemorySize, SMEM_TOTAL);

    __half *xh, *yh, *xp;
    cudaGetSymbolAddress((void**)&xh, g_xh);
    cudaGetSymbolAddress((void**)&yh, g_yh);
    cudaGetSymbolAddress((void**)&xp, g_xp);
    __half *w1, *w2;
    cudaGetSymbolAddress((void**)&w1, g_w1);
    cudaGetSymbolAddress((void**)&w2, g_w2);

    convw_kernel<<<(2 * N4W + 255) / 256, 256>>>(Win, Wout, ap);
    int n4x = (MROWS * DIM) / 4;
    convx_kernel<<<(n4x + 255) / 256, 256>>>(x, xh, n4x);

    dim3 ggrid(DIM / BN, MROWS / BM);
    gemm_mma<__half, true><<<ggrid, 256, SMEM_TOTAL>>>(xh, w1, bin, xp);

    carry_kernel<<<BATCH, DIM>>>(init);
    scan_kernel<<<dim3(NCHUNK, BATCH), DIM>>>(init);

    gemm_mma<float, false><<<ggrid, 256, SMEM_TOTAL>>>(yh, w2, bout, out);
}

// round 15
// speedup vs baseline: 1.0914x; 1.0914x over previous
#include <cuda_runtime.h>
#include <cuda_fp16.h>
#include <math.h>
#include <stdint.h>

// Problem dims (fixed)
#define BATCH 4
#define SEQ   8192
#define DIM   512
#define HEADS 8
#define MROWS (BATCH*SEQ)

// scan chunking
#define CHUNK  128
#define NCHUNK (SEQ/CHUNK)

// ---------------------------------------------------------------------------
// device scratch (allocation-free rule -> __device__ globals)
// ---------------------------------------------------------------------------
__device__ __half g_xp [(size_t)MROWS*DIM];     // GEMM1 output (fp16)
__device__ __half g_xh [(size_t)MROWS*DIM];     // x as fp16
__device__ __half g_yh [(size_t)MROWS*DIM];     // y as fp16
__device__ __half g_w1 [DIM*DIM];               // W_in  fp16
__device__ __half g_w2 [DIM*DIM];               // W_out fp16
__device__ float  g_e  [(size_t)BATCH*NCHUNK*DIM];  // chunk terminals (partial)
__device__ float  g_cin[(size_t)BATCH*NCHUNK*DIM];
__device__ float  g_alpha[HEADS];

// ---------------------------------------------------------------------------
// helpers
// ---------------------------------------------------------------------------
__device__ __forceinline__ uint32_t s2u(const void* p) {
    uint32_t a;
    asm("{ .reg .u64 t; cvta.to.shared.u64 t, %1; cvt.u32.u64 %0, t; }"
        : "=r"(a) : "l"(p));
    return a;
}

__device__ __forceinline__ void ldsm4(uint32_t& r0, uint32_t& r1,
                                      uint32_t& r2, uint32_t& r3,
                                      uint32_t addr) {
    asm volatile("ldmatrix.sync.aligned.m8n8.x4.shared.b16 {%0,%1,%2,%3}, [%4];"
                 : "=r"(r0), "=r"(r1), "=r"(r2), "=r"(r3) : "r"(addr));
}

__device__ __forceinline__ void mma16816(float* c, const uint32_t* a,
                                         const uint32_t* b) {
    asm volatile(
        "mma.sync.aligned.m16n8k16.row.col.f32.f16.f16.f32 "
        "{%0,%1,%2,%3}, {%4,%5,%6,%7}, {%8,%9}, {%0,%1,%2,%3};"
        : "+f"(c[0]), "+f"(c[1]), "+f"(c[2]), "+f"(c[3])
        : "r"(a[0]), "r"(a[1]), "r"(a[2]), "r"(a[3]), "r"(b[0]), "r"(b[1]));
}

// ---------------------------------------------------------------------------
// weight converts (both) + alpha = sigmoid(alpha_param), one launch
// ---------------------------------------------------------------------------
#define N4W (DIM*DIM/4)
__global__ void __launch_bounds__(256)
convw_kernel(const float* __restrict__ Win, const float* __restrict__ Wout,
             const float* __restrict__ ap) {
    int i = blockIdx.x * 256 + threadIdx.x;
    if (blockIdx.x == 0 && threadIdx.x < HEADS)
        g_alpha[threadIdx.x] = 1.0f / (1.0f + expf(-ap[threadIdx.x]));
    const float* src;
    __half* dst;
    int j;
    if (i < N4W)            { src = Win;  dst = g_w1; j = i; }
    else if (i < 2 * N4W)   { src = Wout; dst = g_w2; j = i - N4W; }
    else return;
    float4 v = ((const float4*)src)[j];
    __half2 h0 = __halves2half2(__float2half_rn(v.x), __float2half_rn(v.y));
    __half2 h1 = __halves2half2(__float2half_rn(v.z), __float2half_rn(v.w));
    ((__half2*)(dst + 4*(size_t)j))[0] = h0;
    ((__half2*)(dst + 4*(size_t)j))[1] = h1;
}

// ---------------------------------------------------------------------------
// x fp32 -> fp16 convert
// ---------------------------------------------------------------------------
__global__ void __launch_bounds__(256)
convx_kernel(const float* __restrict__ src, __half* __restrict__ dst, int n4) {
    int i = blockIdx.x * blockDim.x + threadIdx.x;
    if (i >= n4) return;
    float4 v = ((const float4*)src)[i];
    __half2 h0 = __halves2half2(__float2half_rn(v.x), __float2half_rn(v.y));
    __half2 h1 = __halves2half2(__float2half_rn(v.z), __float2half_rn(v.w));
    ((__half2*)(dst + 4*(size_t)i))[0] = h0;
    ((__half2*)(dst + 4*(size_t)i))[1] = h1;
}

// ---------------------------------------------------------------------------
// fp16 HMMA GEMM (R9-proven): C[m,n] = sum_k A[m,k]*B[n,k] + bias[n]
//   CTA 128x128, BK=64, 256 thr (8 warps 2x4), warp tile 64x32.
//   2-stage cp.async; xor swizzle; ldmatrix.x4; mma.m16n8k16.f16; 2 CTAs/SM.
//   DO_E variant (GEMM1): epilogue additionally emits the scan-chunk terminal
//     e'[chunk,col] = alpha*v[127] - alpha^2 * sum_{t<=126} a^(126-t) v[t]
//   (v = acc+bias, fp32). BM==CHUNK so blockIdx.y IS the chunk index.
//   Coefficients via direct powf per term (R13 underflow bug fixed in R14).
// ---------------------------------------------------------------------------
#define BM 128
#define BN 128
#define BK 64
#define KITERS (DIM/BK)     // 8

#define XA_OFF 0
#define BB_OFF 16384
#define STAGE_BYTES 32768
#define SMEM_TOTAL (2*STAGE_BYTES)   // 64 KB

#define TSWZ(row, c16) ((uint32_t)(row) * 128u + 16u * ((uint32_t)(c16) ^ ((uint32_t)(row) & 7u)))

__device__ __forceinline__ void load_stage(uint32_t sbase,
                                           const __half* __restrict__ A,
                                           const __half* __restrict__ B,
                                           int m0, int n0, int k0, int tid) {
#pragma unroll
    for (int q = 0; q < 8; q++) {
        int i = tid + q * 256;
        int mat = i >> 10;            // 0 A, 1 B
        int j = i & 1023;
        int row = j >> 3;
        int c = j & 7;
        const __half* src = (mat ? B + (size_t)(n0 + row) * DIM
                                 : A + (size_t)(m0 + row) * DIM) + k0 + c * 8;
        uint32_t dst = sbase + (mat ? BB_OFF : XA_OFF) + TSWZ(row, c);
        asm volatile("cp.async.cg.shared.global [%0], [%1], 16;"
                     :: "r"(dst), "l"(src));
    }
}

template <typename OutT, bool DO_E>
__global__ void __launch_bounds__(256, 2)
gemm_mma(const __half* __restrict__ A, const __half* __restrict__ B,
         const float* __restrict__ bias, OutT* __restrict__ C) {
    extern __shared__ char smem[];
    uint32_t sb = s2u(smem);

    const int tid  = threadIdx.x;
    const int wid  = tid >> 5;
    const int lane = tid & 31;
    const int wm   = wid >> 2;
    const int wn   = wid & 3;
    const int m0   = blockIdx.y * BM;
    const int n0   = blockIdx.x * BN;

    float acc[4][4][4];
#pragma unroll
    for (int i = 0; i < 4; i++)
#pragma unroll
        for (int j = 0; j < 4; j++)
#pragma unroll
            for (int r = 0; r < 4; r++) acc[i][j][r] = 0.0f;

    const int arow = wm * 64 + (lane & 15);
    const int achk = lane >> 4;
    const int brow = wn * 32 + (lane & 7) + ((lane >> 4) << 3);
    const int bchk = (lane >> 3) & 1;
    const uint32_t sxor = (uint32_t)(lane & 7);

    load_stage(sb, A, B, m0, n0, 0, tid);
    asm volatile("cp.async.commit_group;" ::: "memory");

    for (int it = 0; it < KITERS; it++) {
        if (it + 1 < KITERS) {
            load_stage(sb + ((it + 1) & 1) * STAGE_BYTES,
                       A, B, m0, n0, (it + 1) * BK, tid);
            asm volatile("cp.async.commit_group;" ::: "memory");
            asm volatile("cp.async.wait_group 1;" ::: "memory");
        } else {
            asm volatile("cp.async.wait_group 0;" ::: "memory");
        }
        __syncthreads();

        uint32_t st = sb + (it & 1) * STAGE_BYTES;
#pragma unroll
        for (int ks = 0; ks < BK / 16; ks++) {
            uint32_t av[4][4];
#pragma unroll
            for (int mt = 0; mt < 4; mt++) {
                int row = arow + mt * 16;
                uint32_t co = (uint32_t)(2 * ks + achk) ^ sxor;
                uint32_t off = (uint32_t)row * 128u + co * 16u;
                ldsm4(av[mt][0], av[mt][1], av[mt][2], av[mt][3],
                      st + XA_OFF + off);
            }
            uint32_t bv[4][2];
#pragma unroll
            for (int nt2 = 0; nt2 < 2; nt2++) {
                int row = brow + nt2 * 16;
                uint32_t co = (uint32_t)(2 * ks + bchk) ^ sxor;
                uint32_t off = (uint32_t)row * 128u + co * 16u;
                uint32_t r0, r1, r2, r3;
                ldsm4(r0, r1, r2, r3, st + BB_OFF + off);
                bv[nt2*2][0] = r0; bv[nt2*2][1] = r1;
                bv[nt2*2+1][0] = r2; bv[nt2*2+1][1] = r3;
            }
#pragma unroll
            for (int mt = 0; mt < 4; mt++)
#pragma unroll
                for (int nt = 0; nt < 4; nt++)
                    mma16816(acc[mt][nt], av[mt], bv[nt]);
        }
        __syncthreads();
    }

    // ---- epilogue: C writes (+ optional chunk-terminal reduction) ----
    const int erow = m0 + wm * 64 + (lane >> 2);
    const int ecol = n0 + wn * 32 + 2 * (lane & 3);

    float ecl[8];
    float coef0[4], coef1[4];
    if (DO_E) {
        const float alpha = g_alpha[(n0 + wn * 32) >> 6];  // warp cols = 1 head
        const float a = 1.0f - alpha;
        const float na2 = -alpha * alpha;
        const int rbase = wm * 64 + (lane >> 2);
#pragma unroll
        for (int mt = 0; mt < 4; mt++) {
            int t0 = rbase + mt * 16;
            int t1 = t0 + 8;
            coef0[mt] = na2 * powf(a, (float)(126 - t0));   // t0 <= 119
            coef1[mt] = (t1 == 127) ? alpha
                                    : na2 * powf(a, (float)(126 - t1));
        }
#pragma unroll
        for (int k = 0; k < 8; k++) ecl[k] = 0.0f;
    }

#pragma unroll
    for (int nt = 0; nt < 4; nt++) {
        int col = ecol + nt * 8;
        float b0 = bias[col], b1 = bias[col + 1];
#pragma unroll
        for (int mt = 0; mt < 4; mt++) {
            int row = erow + mt * 16;
            float v00 = acc[mt][nt][0] + b0, v01 = acc[mt][nt][1] + b1;
            float v10 = acc[mt][nt][2] + b0, v11 = acc[mt][nt][3] + b1;
            if (sizeof(OutT) == 4) {
                *(float2*)((float*)C + (size_t)row * DIM + col)
                    = make_float2(v00, v01);
                *(float2*)((float*)C + (size_t)(row + 8) * DIM + col)
                    = make_float2(v10, v11);
            } else {
                *(__half2*)((__half*)C + (size_t)row * DIM + col)
                    = __halves2half2(__float2half_rn(v00), __float2half_rn(v01));
                *(__half2*)((__half*)C + (size_t)(row + 8) * DIM + col)
                    = __halves2half2(__float2half_rn(v10), __float2half_rn(v11));
            }
            if (DO_E) {
                ecl[nt*2+0] += coef0[mt] * v00 + coef1[mt] * v10;
                ecl[nt*2+1] += coef0[mt] * v01 + coef1[mt] * v11;
            }
        }
    }

    if (DO_E) {
#pragma unroll
        for (int k = 0; k < 8; k++) {
#pragma unroll
            for (int s = 4; s < 32; s <<= 1)
                ecl[k] += __shfl_xor_sync(0xffffffffu, ecl[k], s);
        }
        float* esh = (float*)smem;   // [2][128] partials per wm
        if ((lane >> 2) == 0) {
#pragma unroll
            for (int k = 0; k < 8; k++) {
                int colw = wn * 32 + (k >> 1) * 8 + 2 * (lane & 3) + (k & 1);
                esh[wm * 128 + colw] = ecl[k];
            }
        }
        __syncthreads();
        if (tid < 128) {
            float e = esh[tid] + esh[128 + tid];
            g_e[(size_t)blockIdx.y * DIM + n0 + tid] = e;
        }
    }
}

// ---------------------------------------------------------------------------
// carry: cin[c] = scan state at chunk start. e[c] = e'[c] - alpha*a^127*xp[-1].
// MLP-preload version: all 64 e and 64 boundary-xp loads issued independently
// before the serial fold (R14's in-loop loads were latency-bound: 37.9 us).
// grid (2, BATCH) x 256 threads; d = blockIdx.x*256 + tid.
// ---------------------------------------------------------------------------
__global__ void __launch_bounds__(256)
carry_kernel(const float* __restrict__ init_state) {
    int d = blockIdx.x * 256 + threadIdx.x;
    int b = blockIdx.y;
    float alpha = g_alpha[d >> 6];
    float a = 1.0f - alpha;
    float aN = powf(a, (float)CHUNK);
    float ca127 = alpha * powf(a, 127.0f);
    float init = init_state[d];

    float e[NCHUNK];
#pragma unroll
    for (int c = 0; c < NCHUNK; c++)
        e[c] = g_e[((size_t)b * NCHUNK + c) * DIM + d];
    float pl[NCHUNK];
    pl[0] = init;
#pragma unroll
    for (int c = 1; c < NCHUNK; c++)
        pl[c] = __half2float(g_xp[((size_t)b * SEQ + c * CHUNK - 1) * DIM + d]);

    float carry = init;
#pragma unroll
    for (int c = 0; c < NCHUNK; c++) {
        g_cin[((size_t)b * NCHUNK + c) * DIM + d] = carry;
        carry = fmaf(aN, carry, fmaf(-ca127, pl[c], e[c]));
    }
}

// ---------------------------------------------------------------------------
// scan: y[t] = a*y[t-1] + alpha*(xp[t]-xp[t-1]), seeded by cin; emit fp16
// ---------------------------------------------------------------------------
__global__ void scan_kernel(const float* __restrict__ init_state) {
    int d = threadIdx.x;
    int c = blockIdx.x, b = blockIdx.y;
    float alpha = g_alpha[d >> 6];
    float a = 1.0f - alpha;
    int t0 = c * CHUNK;
    size_t off = ((size_t)b * SEQ + t0) * DIM + d;
    const __half* base = g_xp + off;
    __half* y = g_yh + off;
    float prev = (t0 == 0) ? init_state[d] : __half2float(*(base - DIM));
    float l = g_cin[((size_t)b * NCHUNK + c) * DIM + d];
#pragma unroll 4
    for (int t = 0; t < CHUNK; t++) {
        float cur = __half2float(base[(size_t)t * DIM]);
        l = a * l + alpha * (cur - prev);
        prev = cur;
        y[(size_t)t * DIM] = __float2half_rn(l);
    }
}

// ---------------------------------------------------------------------------
// launch
// ---------------------------------------------------------------------------
extern "C" void kernel_launch(void* const* d_in, const int* in_sizes, int n_in,
                              void* d_out, int out_size) {
    const float* x    = (const float*)d_in[0];
    const float* Win  = (const float*)d_in[1];
    const float* bin  = (const float*)d_in[2];
    const float* Wout = (const float*)d_in[3];
    const float* bout = (const float*)d_in[4];
    const float* init = (const float*)d_in[5];
    const float* ap   = (const float*)d_in[6];
    float* out = (float*)d_out;

    cudaFuncSetAttribute((const void*)gemm_mma<__half, true>,
                         cudaFuncAttributeMaxDynamicSharedMemorySize, SMEM_TOTAL);
    cudaFuncSetAttribute((const void*)gemm_mma<float, false>,
                         cudaFuncAttributeMaxDynamicSharedMemorySize, SMEM_TOTAL);

    __half *xh, *yh, *xp;
    cudaGetSymbolAddress((void**)&xh, g_xh);
    cudaGetSymbolAddress((void**)&yh, g_yh);
    cudaGetSymbolAddress((void**)&xp, g_xp);
    __half *w1, *w2;
    cudaGetSymbolAddress((void**)&w1, g_w1);
    cudaGetSymbolAddress((void**)&w2, g_w2);

    convw_kernel<<<(2 * N4W + 255) / 256, 256>>>(Win, Wout, ap);
    int n4x = (MROWS * DIM) / 4;
    convx_kernel<<<(n4x + 255) / 256, 256>>>(x, xh, n4x);

    dim3 ggrid(DIM / BN, MROWS / BM);
    gemm_mma<__half, true><<<ggrid, 256, SMEM_TOTAL>>>(xh, w1, bin, xp);

    carry_kernel<<<dim3(2, BATCH), 256>>>(init);
    scan_kernel<<<dim3(NCHUNK, BATCH), DIM>>>(init);

    gemm_mma<float, false><<<ggrid, 256, SMEM_TOTAL>>>(yh, w2, bout, out);
}

// round 16
// speedup vs baseline: 1.2053x; 1.1043x over previous
#include <cuda_runtime.h>
#include <cuda_fp16.h>
#include <math.h>
#include <stdint.h>

// Problem dims (fixed)
#define BATCH 4
#define SEQ   8192
#define DIM   512
#define HEADS 8
#define MROWS (BATCH*SEQ)

// scan chunking
#define CHUNK  128
#define NCHUNK (SEQ/CHUNK)

// ---------------------------------------------------------------------------
// device scratch (allocation-free rule -> __device__ globals)
// ---------------------------------------------------------------------------
__device__ __half g_xp [(size_t)MROWS*DIM];     // GEMM1 output (fp16)
__device__ __half g_xh [(size_t)MROWS*DIM];     // x as fp16
__device__ __half g_yh [(size_t)MROWS*DIM];     // y as fp16
__device__ __half g_w1 [DIM*DIM];               // W_in  fp16
__device__ __half g_w2 [DIM*DIM];               // W_out fp16
__device__ float  g_e  [(size_t)BATCH*NCHUNK*DIM];
__device__ float  g_cin[(size_t)BATCH*NCHUNK*DIM];
__device__ float  g_alpha[HEADS];

// ---------------------------------------------------------------------------
// helpers
// ---------------------------------------------------------------------------
__device__ __forceinline__ uint32_t s2u(const void* p) {
    uint32_t a;
    asm("{ .reg .u64 t; cvta.to.shared.u64 t, %1; cvt.u32.u64 %0, t; }"
        : "=r"(a) : "l"(p));
    return a;
}

__device__ __forceinline__ void ldsm4(uint32_t& r0, uint32_t& r1,
                                      uint32_t& r2, uint32_t& r3,
                                      uint32_t addr) {
    asm volatile("ldmatrix.sync.aligned.m8n8.x4.shared.b16 {%0,%1,%2,%3}, [%4];"
                 : "=r"(r0), "=r"(r1), "=r"(r2), "=r"(r3) : "r"(addr));
}

__device__ __forceinline__ void mma16816(float* c, const uint32_t* a,
                                         const uint32_t* b) {
    asm volatile(
        "mma.sync.aligned.m16n8k16.row.col.f32.f16.f16.f32 "
        "{%0,%1,%2,%3}, {%4,%5,%6,%7}, {%8,%9}, {%0,%1,%2,%3};"
        : "+f"(c[0]), "+f"(c[1]), "+f"(c[2]), "+f"(c[3])
        : "r"(a[0]), "r"(a[1]), "r"(a[2]), "r"(a[3]), "r"(b[0]), "r"(b[1]));
}

// ---------------------------------------------------------------------------
// weight converts (both) + alpha = sigmoid(alpha_param), one launch
// ---------------------------------------------------------------------------
#define N4W (DIM*DIM/4)
__global__ void __launch_bounds__(256)
convw_kernel(const float* __restrict__ Win, const float* __restrict__ Wout,
             const float* __restrict__ ap) {
    int i = blockIdx.x * 256 + threadIdx.x;
    if (blockIdx.x == 0 && threadIdx.x < HEADS)
        g_alpha[threadIdx.x] = 1.0f / (1.0f + expf(-ap[threadIdx.x]));
    const float* src;
    __half* dst;
    int j;
    if (i < N4W)            { src = Win;  dst = g_w1; j = i; }
    else if (i < 2 * N4W)   { src = Wout; dst = g_w2; j = i - N4W; }
    else return;
    float4 v = ((const float4*)src)[j];
    __half2 h0 = __halves2half2(__float2half_rn(v.x), __float2half_rn(v.y));
    __half2 h1 = __halves2half2(__float2half_rn(v.z), __float2half_rn(v.w));
    ((__half2*)(dst + 4*(size_t)j))[0] = h0;
    ((__half2*)(dst + 4*(size_t)j))[1] = h1;
}

// ---------------------------------------------------------------------------
// x fp32 -> fp16 convert
// ---------------------------------------------------------------------------
__global__ void __launch_bounds__(256)
convx_kernel(const float* __restrict__ src, __half* __restrict__ dst, int n4) {
    int i = blockIdx.x * blockDim.x + threadIdx.x;
    if (i >= n4) return;
    float4 v = ((const float4*)src)[i];
    __half2 h0 = __halves2half2(__float2half_rn(v.x), __float2half_rn(v.y));
    __half2 h1 = __halves2half2(__float2half_rn(v.z), __float2half_rn(v.w));
    ((__half2*)(dst + 4*(size_t)i))[0] = h0;
    ((__half2*)(dst + 4*(size_t)i))[1] = h1;
}

// ---------------------------------------------------------------------------
// fp16 HMMA GEMM (R9-proven, plain): C[m,n] = sum_k A[m,k]*B[n,k] + bias[n]
//   CTA 128x128, BK=64, 256 thr (8 warps 2x4), warp tile 64x32.
//   2-stage cp.async; xor swizzle; ldmatrix.x4; mma.m16n8k16.f16; 2 CTAs/SM.
// ---------------------------------------------------------------------------
#define BM 128
#define BN 128
#define BK 64
#define KITERS (DIM/BK)     // 8

#define XA_OFF 0
#define BB_OFF 16384
#define STAGE_BYTES 32768
#define SMEM_TOTAL (2*STAGE_BYTES)   // 64 KB

#define TSWZ(row, c16) ((uint32_t)(row) * 128u + 16u * ((uint32_t)(c16) ^ ((uint32_t)(row) & 7u)))

__device__ __forceinline__ void load_stage(uint32_t sbase,
                                           const __half* __restrict__ A,
                                           const __half* __restrict__ B,
                                           int m0, int n0, int k0, int tid) {
#pragma unroll
    for (int q = 0; q < 8; q++) {
        int i = tid + q * 256;
        int mat = i >> 10;            // 0 A, 1 B
        int j = i & 1023;
        int row = j >> 3;
        int c = j & 7;
        const __half* src = (mat ? B + (size_t)(n0 + row) * DIM
                                 : A + (size_t)(m0 + row) * DIM) + k0 + c * 8;
        uint32_t dst = sbase + (mat ? BB_OFF : XA_OFF) + TSWZ(row, c);
        asm volatile("cp.async.cg.shared.global [%0], [%1], 16;"
                     :: "r"(dst), "l"(src));
    }
}

template <typename OutT>
__global__ void __launch_bounds__(256, 2)
gemm_mma(const __half* __restrict__ A, const __half* __restrict__ B,
         const float* __restrict__ bias, OutT* __restrict__ C) {
    extern __shared__ char smem[];
    uint32_t sb = s2u(smem);

    const int tid  = threadIdx.x;
    const int wid  = tid >> 5;
    const int lane = tid & 31;
    const int wm   = wid >> 2;
    const int wn   = wid & 3;
    const int m0   = blockIdx.y * BM;
    const int n0   = blockIdx.x * BN;

    float acc[4][4][4];
#pragma unroll
    for (int i = 0; i < 4; i++)
#pragma unroll
        for (int j = 0; j < 4; j++)
#pragma unroll
            for (int r = 0; r < 4; r++) acc[i][j][r] = 0.0f;

    const int arow = wm * 64 + (lane & 15);
    const int achk = lane >> 4;
    const int brow = wn * 32 + (lane & 7) + ((lane >> 4) << 3);
    const int bchk = (lane >> 3) & 1;
    const uint32_t sxor = (uint32_t)(lane & 7);

    load_stage(sb, A, B, m0, n0, 0, tid);
    asm volatile("cp.async.commit_group;" ::: "memory");

    for (int it = 0; it < KITERS; it++) {
        if (it + 1 < KITERS) {
            load_stage(sb + ((it + 1) & 1) * STAGE_BYTES,
                       A, B, m0, n0, (it + 1) * BK, tid);
            asm volatile("cp.async.commit_group;" ::: "memory");
            asm volatile("cp.async.wait_group 1;" ::: "memory");
        } else {
            asm volatile("cp.async.wait_group 0;" ::: "memory");
        }
        __syncthreads();

        uint32_t st = sb + (it & 1) * STAGE_BYTES;
#pragma unroll
        for (int ks = 0; ks < BK / 16; ks++) {
            uint32_t av[4][4];
#pragma unroll
            for (int mt = 0; mt < 4; mt++) {
                int row = arow + mt * 16;
                uint32_t co = (uint32_t)(2 * ks + achk) ^ sxor;
                uint32_t off = (uint32_t)row * 128u + co * 16u;
                ldsm4(av[mt][0], av[mt][1], av[mt][2], av[mt][3],
                      st + XA_OFF + off);
            }
            uint32_t bv[4][2];
#pragma unroll
            for (int nt2 = 0; nt2 < 2; nt2++) {
                int row = brow + nt2 * 16;
                uint32_t co = (uint32_t)(2 * ks + bchk) ^ sxor;
                uint32_t off = (uint32_t)row * 128u + co * 16u;
                uint32_t r0, r1, r2, r3;
                ldsm4(r0, r1, r2, r3, st + BB_OFF + off);
                bv[nt2*2][0] = r0; bv[nt2*2][1] = r1;
                bv[nt2*2+1][0] = r2; bv[nt2*2+1][1] = r3;
            }
#pragma unroll
            for (int mt = 0; mt < 4; mt++)
#pragma unroll
                for (int nt = 0; nt < 4; nt++)
                    mma16816(acc[mt][nt], av[mt], bv[nt]);
        }
        __syncthreads();
    }

    const int erow = m0 + wm * 64 + (lane >> 2);
    const int ecol = n0 + wn * 32 + 2 * (lane & 3);
#pragma unroll
    for (int nt = 0; nt < 4; nt++) {
        int col = ecol + nt * 8;
        float b0 = bias[col], b1 = bias[col + 1];
#pragma unroll
        for (int mt = 0; mt < 4; mt++) {
            int row = erow + mt * 16;
            float v00 = acc[mt][nt][0] + b0, v01 = acc[mt][nt][1] + b1;
            float v10 = acc[mt][nt][2] + b0, v11 = acc[mt][nt][3] + b1;
            if (sizeof(OutT) == 4) {
                *(float2*)((float*)C + (size_t)row * DIM + col)
                    = make_float2(v00, v01);
                *(float2*)((float*)C + (size_t)(row + 8) * DIM + col)
                    = make_float2(v10, v11);
            } else {
                *(__half2*)((__half*)C + (size_t)row * DIM + col)
                    = __halves2half2(__float2half_rn(v00), __float2half_rn(v01));
                *(__half2*)((__half*)C + (size_t)(row + 8) * DIM + col)
                    = __halves2half2(__float2half_rn(v10), __float2half_rn(v11));
            }
        }
    }
}

// ---------------------------------------------------------------------------
// chunk_end: per-chunk terminal of the zero-seeded local scan (reads fp16 xp)
// ---------------------------------------------------------------------------
__global__ void chunk_end_kernel(const float* __restrict__ init_state) {
    int d = threadIdx.x;
    int c = blockIdx.x, b = blockIdx.y;
    float alpha = g_alpha[d >> 6];
    float a = 1.0f - alpha;
    int t0 = c * CHUNK;
    const __half* base = g_xp + ((size_t)b * SEQ + t0) * DIM + d;
    float prev = (t0 == 0) ? init_state[d] : __half2float(*(base - DIM));
    float l = 0.0f;
#pragma unroll 4
    for (int t = 0; t < CHUNK; t++) {
        float cur = __half2float(base[(size_t)t * DIM]);
        l = a * l + alpha * (cur - prev);
        prev = cur;
    }
    g_e[((size_t)b * NCHUNK + c) * DIM + d] = l;
}

// ---------------------------------------------------------------------------
// carry: MLP-preload e[64] into regs, then serial fold. 8 blocks x 256 thr.
// ---------------------------------------------------------------------------
__global__ void __launch_bounds__(256)
carry_kernel(const float* __restrict__ init_state) {
    int d = blockIdx.x * 256 + threadIdx.x;
    int b = blockIdx.y;
    float a = 1.0f - g_alpha[d >> 6];
    float aN = powf(a, (float)CHUNK);
    float e[NCHUNK];
#pragma unroll
    for (int c = 0; c < NCHUNK; c++)
        e[c] = g_e[((size_t)b * NCHUNK + c) * DIM + d];
    float carry = init_state[d];
#pragma unroll
    for (int c = 0; c < NCHUNK; c++) {
        g_cin[((size_t)b * NCHUNK + c) * DIM + d] = carry;
        carry = fmaf(aN, carry, e[c]);
    }
}

// ---------------------------------------------------------------------------
// scan: y[t] = a*y[t-1] + alpha*(xp[t]-xp[t-1]), seeded by cin; emit fp16
// ---------------------------------------------------------------------------
__global__ void scan_kernel(const float* __restrict__ init_state) {
    int d = threadIdx.x;
    int c = blockIdx.x, b = blockIdx.y;
    float alpha = g_alpha[d >> 6];
    float a = 1.0f - alpha;
    int t0 = c * CHUNK;
    size_t off = ((size_t)b * SEQ + t0) * DIM + d;
    const __half* base = g_xp + off;
    __half* y = g_yh + off;
    float prev = (t0 == 0) ? init_state[d] : __half2float(*(base - DIM));
    float l = g_cin[((size_t)b * NCHUNK + c) * DIM + d];
#pragma unroll 4
    for (int t = 0; t < CHUNK; t++) {
        float cur = __half2float(base[(size_t)t * DIM]);
        l = a * l + alpha * (cur - prev);
        prev = cur;
        y[(size_t)t * DIM] = __float2half_rn(l);
    }
}

// ---------------------------------------------------------------------------
// launch
// ---------------------------------------------------------------------------
extern "C" void kernel_launch(void* const* d_in, const int* in_sizes, int n_in,
                              void* d_out, int out_size) {
    const float* x    = (const float*)d_in[0];
    const float* Win  = (const float*)d_in[1];
    const float* bin  = (const float*)d_in[2];
    const float* Wout = (const float*)d_in[3];
    const float* bout = (const float*)d_in[4];
    const float* init = (const float*)d_in[5];
    const float* ap   = (const float*)d_in[6];
    float* out = (float*)d_out;

    cudaFuncSetAttribute((const void*)gemm_mma<__half>,
                         cudaFuncAttributeMaxDynamicSharedMemorySize, SMEM_TOTAL);
    cudaFuncSetAttribute((const void*)gemm_mma<float>,
                         cudaFuncAttributeMaxDynamicSharedMemorySize, SMEM_TOTAL);

    __half *xh, *yh, *xp, *w1, *w2;
    cudaGetSymbolAddress((void**)&xh, g_xh);
    cudaGetSymbolAddress((void**)&yh, g_yh);
    cudaGetSymbolAddress((void**)&xp, g_xp);
    cudaGetSymbolAddress((void**)&w1, g_w1);
    cudaGetSymbolAddress((void**)&w2, g_w2);

    convw_kernel<<<(2 * N4W + 255) / 256, 256>>>(Win, Wout, ap);
    int n4x = (MROWS * DIM) / 4;
    convx_kernel<<<(n4x + 255) / 256, 256>>>(x, xh, n4x);

    dim3 ggrid(DIM / BN, MROWS / BM);
    gemm_mma<__half><<<ggrid, 256, SMEM_TOTAL>>>(xh, w1, bin, xp);

    chunk_end_kernel<<<dim3(NCHUNK, BATCH), DIM>>>(init);
    carry_kernel<<<dim3(2, BATCH), 256>>>(init);
    scan_kernel<<<dim3(NCHUNK, BATCH), DIM>>>(init);

    gemm_mma<float><<<ggrid, 256, SMEM_TOTAL>>>(yh, w2, bout, out);
}

// round 17
// speedup vs baseline: 1.2185x; 1.0109x over previous
#include <cuda_runtime.h>
#include <cuda_fp16.h>
#include <math.h>
#include <stdint.h>

// Problem dims (fixed)
#define BATCH 4
#define SEQ   8192
#define DIM   512
#define HEADS 8
#define MROWS (BATCH*SEQ)

// scan chunking
#define CHUNK  128
#define NCHUNK (SEQ/CHUNK)

// ---------------------------------------------------------------------------
// device scratch (allocation-free rule -> __device__ globals)
// ---------------------------------------------------------------------------
__device__ __half g_xp [(size_t)MROWS*DIM];     // GEMM1 output (fp16)
__device__ __half g_xh [(size_t)MROWS*DIM];     // x as fp16
__device__ __half g_yh [(size_t)MROWS*DIM];     // y as fp16
__device__ __half g_w1 [DIM*DIM];               // W_in  fp16
__device__ __half g_w2 [DIM*DIM];               // W_out fp16
__device__ float  g_e  [(size_t)BATCH*NCHUNK*DIM];
__device__ float  g_cin[(size_t)BATCH*NCHUNK*DIM];
__device__ float  g_alpha[HEADS];

// ---------------------------------------------------------------------------
// helpers
// ---------------------------------------------------------------------------
__device__ __forceinline__ uint32_t s2u(const void* p) {
    uint32_t a;
    asm("{ .reg .u64 t; cvta.to.shared.u64 t, %1; cvt.u32.u64 %0, t; }"
        : "=r"(a) : "l"(p));
    return a;
}

__device__ __forceinline__ void ldsm4(uint32_t& r0, uint32_t& r1,
                                      uint32_t& r2, uint32_t& r3,
                                      uint32_t addr) {
    asm volatile("ldmatrix.sync.aligned.m8n8.x4.shared.b16 {%0,%1,%2,%3}, [%4];"
                 : "=r"(r0), "=r"(r1), "=r"(r2), "=r"(r3) : "r"(addr));
}

__device__ __forceinline__ void mma16816(float* c, const uint32_t* a,
                                         const uint32_t* b) {
    asm volatile(
        "mma.sync.aligned.m16n8k16.row.col.f32.f16.f16.f32 "
        "{%0,%1,%2,%3}, {%4,%5,%6,%7}, {%8,%9}, {%0,%1,%2,%3};"
        : "+f"(c[0]), "+f"(c[1]), "+f"(c[2]), "+f"(c[3])
        : "r"(a[0]), "r"(a[1]), "r"(a[2]), "r"(a[3]), "r"(b[0]), "r"(b[1]));
}

// ---------------------------------------------------------------------------
// weight converts (both) + alpha = sigmoid(alpha_param), one launch
// ---------------------------------------------------------------------------
#define N4W (DIM*DIM/4)
__global__ void __launch_bounds__(256)
convw_kernel(const float* __restrict__ Win, const float* __restrict__ Wout,
             const float* __restrict__ ap) {
    int i = blockIdx.x * 256 + threadIdx.x;
    if (blockIdx.x == 0 && threadIdx.x < HEADS)
        g_alpha[threadIdx.x] = 1.0f / (1.0f + expf(-ap[threadIdx.x]));
    const float* src;
    __half* dst;
    int j;
    if (i < N4W)            { src = Win;  dst = g_w1; j = i; }
    else if (i < 2 * N4W)   { src = Wout; dst = g_w2; j = i - N4W; }
    else return;
    float4 v = ((const float4*)src)[j];
    __half2 h0 = __halves2half2(__float2half_rn(v.x), __float2half_rn(v.y));
    __half2 h1 = __halves2half2(__float2half_rn(v.z), __float2half_rn(v.w));
    ((__half2*)(dst + 4*(size_t)j))[0] = h0;
    ((__half2*)(dst + 4*(size_t)j))[1] = h1;
}

// ---------------------------------------------------------------------------
// x fp32 -> fp16 convert
// ---------------------------------------------------------------------------
__global__ void __launch_bounds__(256)
convx_kernel(const float* __restrict__ src, __half* __restrict__ dst, int n4) {
    int i = blockIdx.x * blockDim.x + threadIdx.x;
    if (i >= n4) return;
    float4 v = ((const float4*)src)[i];
    __half2 h0 = __halves2half2(__float2half_rn(v.x), __float2half_rn(v.y));
    __half2 h1 = __halves2half2(__float2half_rn(v.z), __float2half_rn(v.w));
    ((__half2*)(dst + 4*(size_t)i))[0] = h0;
    ((__half2*)(dst + 4*(size_t)i))[1] = h1;
}

// ---------------------------------------------------------------------------
// fp16 HMMA GEMM (R9-proven, plain): C[m,n] = sum_k A[m,k]*B[n,k] + bias[n]
//   CTA 128x128, BK=64, 256 thr (8 warps 2x4), warp tile 64x32.
//   2-stage cp.async; xor swizzle; ldmatrix.x4; mma.m16n8k16.f16; 2 CTAs/SM.
// ---------------------------------------------------------------------------
#define BM 128
#define BN 128
#define BK 64
#define KITERS (DIM/BK)     // 8

#define XA_OFF 0
#define BB_OFF 16384
#define STAGE_BYTES 32768
#define SMEM_TOTAL (2*STAGE_BYTES)   // 64 KB

#define TSWZ(row, c16) ((uint32_t)(row) * 128u + 16u * ((uint32_t)(c16) ^ ((uint32_t)(row) & 7u)))

__device__ __forceinline__ void load_stage(uint32_t sbase,
                                           const __half* __restrict__ A,
                                           const __half* __restrict__ B,
                                           int m0, int n0, int k0, int tid) {
#pragma unroll
    for (int q = 0; q < 8; q++) {
        int i = tid + q * 256;
        int mat = i >> 10;            // 0 A, 1 B
        int j = i & 1023;
        int row = j >> 3;
        int c = j & 7;
        const __half* src = (mat ? B + (size_t)(n0 + row) * DIM
                                 : A + (size_t)(m0 + row) * DIM) + k0 + c * 8;
        uint32_t dst = sbase + (mat ? BB_OFF : XA_OFF) + TSWZ(row, c);
        asm volatile("cp.async.cg.shared.global [%0], [%1], 16;"
                     :: "r"(dst), "l"(src));
    }
}

template <typename OutT>
__global__ void __launch_bounds__(256, 2)
gemm_mma(const __half* __restrict__ A, const __half* __restrict__ B,
         const float* __restrict__ bias, OutT* __restrict__ C) {
    extern __shared__ char smem[];
    uint32_t sb = s2u(smem);

    const int tid  = threadIdx.x;
    const int wid  = tid >> 5;
    const int lane = tid & 31;
    const int wm   = wid >> 2;
    const int wn   = wid & 3;
    const int m0   = blockIdx.y * BM;
    const int n0   = blockIdx.x * BN;

    float acc[4][4][4];
#pragma unroll
    for (int i = 0; i < 4; i++)
#pragma unroll
        for (int j = 0; j < 4; j++)
#pragma unroll
            for (int r = 0; r < 4; r++) acc[i][j][r] = 0.0f;

    const int arow = wm * 64 + (lane & 15);
    const int achk = lane >> 4;
    const int brow = wn * 32 + (lane & 7) + ((lane >> 4) << 3);
    const int bchk = (lane >> 3) & 1;
    const uint32_t sxor = (uint32_t)(lane & 7);

    load_stage(sb, A, B, m0, n0, 0, tid);
    asm volatile("cp.async.commit_group;" ::: "memory");

    for (int it = 0; it < KITERS; it++) {
        if (it + 1 < KITERS) {
            load_stage(sb + ((it + 1) & 1) * STAGE_BYTES,
                       A, B, m0, n0, (it + 1) * BK, tid);
            asm volatile("cp.async.commit_group;" ::: "memory");
            asm volatile("cp.async.wait_group 1;" ::: "memory");
        } else {
            asm volatile("cp.async.wait_group 0;" ::: "memory");
        }
        __syncthreads();

        uint32_t st = sb + (it & 1) * STAGE_BYTES;
#pragma unroll
        for (int ks = 0; ks < BK / 16; ks++) {
            uint32_t av[4][4];
#pragma unroll
            for (int mt = 0; mt < 4; mt++) {
                int row = arow + mt * 16;
                uint32_t co = (uint32_t)(2 * ks + achk) ^ sxor;
                uint32_t off = (uint32_t)row * 128u + co * 16u;
                ldsm4(av[mt][0], av[mt][1], av[mt][2], av[mt][3],
                      st + XA_OFF + off);
            }
            uint32_t bv[4][2];
#pragma unroll
            for (int nt2 = 0; nt2 < 2; nt2++) {
                int row = brow + nt2 * 16;
                uint32_t co = (uint32_t)(2 * ks + bchk) ^ sxor;
                uint32_t off = (uint32_t)row * 128u + co * 16u;
                uint32_t r0, r1, r2, r3;
                ldsm4(r0, r1, r2, r3, st + BB_OFF + off);
                bv[nt2*2][0] = r0; bv[nt2*2][1] = r1;
                bv[nt2*2+1][0] = r2; bv[nt2*2+1][1] = r3;
            }
#pragma unroll
            for (int mt = 0; mt < 4; mt++)
#pragma unroll
                for (int nt = 0; nt < 4; nt++)
                    mma16816(acc[mt][nt], av[mt], bv[nt]);
        }
        __syncthreads();
    }

    const int erow = m0 + wm * 64 + (lane >> 2);
    const int ecol = n0 + wn * 32 + 2 * (lane & 3);
#pragma unroll
    for (int nt = 0; nt < 4; nt++) {
        int col = ecol + nt * 8;
        float b0 = bias[col], b1 = bias[col + 1];
#pragma unroll
        for (int mt = 0; mt < 4; mt++) {
            int row = erow + mt * 16;
            float v00 = acc[mt][nt][0] + b0, v01 = acc[mt][nt][1] + b1;
            float v10 = acc[mt][nt][2] + b0, v11 = acc[mt][nt][3] + b1;
            if (sizeof(OutT) == 4) {
                *(float2*)((float*)C + (size_t)row * DIM + col)
                    = make_float2(v00, v01);
                *(float2*)((float*)C + (size_t)(row + 8) * DIM + col)
                    = make_float2(v10, v11);
            } else {
                *(__half2*)((__half*)C + (size_t)row * DIM + col)
                    = __halves2half2(__float2half_rn(v00), __float2half_rn(v01));
                *(__half2*)((__half*)C + (size_t)(row + 8) * DIM + col)
                    = __halves2half2(__float2half_rn(v10), __float2half_rn(v11));
            }
        }
    }
}

// ---------------------------------------------------------------------------
// chunk_end: per-chunk terminal of the zero-seeded local scan.
// __half2 datapath: thread handles 2 adjacent channels (same head -> same a).
// 256 threads/block; 4-byte loads; 2 independent FMA chains per thread.
// ---------------------------------------------------------------------------
__global__ void __launch_bounds__(256)
chunk_end_kernel(const float* __restrict__ init_state) {
    int p = threadIdx.x;               // pair index 0..255
    int d = p * 2;
    int c = blockIdx.x, b = blockIdx.y;
    float alpha = g_alpha[d >> 6];
    float a = 1.0f - alpha;
    int t0 = c * CHUNK;
    const __half2* base = (const __half2*)(g_xp + ((size_t)b * SEQ + t0) * DIM + d);
    const int str = DIM / 2;
    float p0, p1;
    if (t0 == 0) {
        p0 = init_state[d]; p1 = init_state[d + 1];
    } else {
        float2 v = __half22float2(*(base - str));
        p0 = v.x; p1 = v.y;
    }
    float l0 = 0.0f, l1 = 0.0f;
#pragma unroll 8
    for (int t = 0; t < CHUNK; t++) {
        float2 cur = __half22float2(base[(size_t)t * str]);
        l0 = a * l0 + alpha * (cur.x - p0);
        l1 = a * l1 + alpha * (cur.y - p1);
        p0 = cur.x; p1 = cur.y;
    }
    size_t eo = ((size_t)b * NCHUNK + c) * DIM + d;
    g_e[eo] = l0;
    g_e[eo + 1] = l1;
}

// ---------------------------------------------------------------------------
// carry: MLP-preload e[64] into regs, then serial fold. 8 blocks x 256 thr.
// ---------------------------------------------------------------------------
__global__ void __launch_bounds__(256)
carry_kernel(const float* __restrict__ init_state) {
    int d = blockIdx.x * 256 + threadIdx.x;
    int b = blockIdx.y;
    float a = 1.0f - g_alpha[d >> 6];
    float aN = powf(a, (float)CHUNK);
    float e[NCHUNK];
#pragma unroll
    for (int c = 0; c < NCHUNK; c++)
        e[c] = g_e[((size_t)b * NCHUNK + c) * DIM + d];
    float carry = init_state[d];
#pragma unroll
    for (int c = 0; c < NCHUNK; c++) {
        g_cin[((size_t)b * NCHUNK + c) * DIM + d] = carry;
        carry = fmaf(aN, carry, e[c]);
    }
}

// ---------------------------------------------------------------------------
// scan: y[t] = a*y[t-1] + alpha*(xp[t]-xp[t-1]), seeded by cin; emit fp16.
// __half2 datapath (2 channels/thread), 256 threads/block.
// ---------------------------------------------------------------------------
__global__ void __launch_bounds__(256)
scan_kernel(const float* __restrict__ init_state) {
    int p = threadIdx.x;
    int d = p * 2;
    int c = blockIdx.x, b = blockIdx.y;
    float alpha = g_alpha[d >> 6];
    float a = 1.0f - alpha;
    int t0 = c * CHUNK;
    size_t off = ((size_t)b * SEQ + t0) * DIM + d;
    const __half2* base = (const __half2*)(g_xp + off);
    __half2* y = (__half2*)(g_yh + off);
    const int str = DIM / 2;
    float p0, p1;
    if (t0 == 0) {
        p0 = init_state[d]; p1 = init_state[d + 1];
    } else {
        float2 v = __half22float2(*(base - str));
        p0 = v.x; p1 = v.y;
    }
    size_t co = ((size_t)b * NCHUNK + c) * DIM + d;
    float l0 = g_cin[co], l1 = g_cin[co + 1];
#pragma unroll 8
    for (int t = 0; t < CHUNK; t++) {
        float2 cur = __half22float2(base[(size_t)t * str]);
        l0 = a * l0 + alpha * (cur.x - p0);
        l1 = a * l1 + alpha * (cur.y - p1);
        p0 = cur.x; p1 = cur.y;
        y[(size_t)t * str] = __halves2half2(__float2half_rn(l0),
                                            __float2half_rn(l1));
    }
}

// ---------------------------------------------------------------------------
// launch
// ---------------------------------------------------------------------------
extern "C" void kernel_launch(void* const* d_in, const int* in_sizes, int n_in,
                              void* d_out, int out_size) {
    const float* x    = (const float*)d_in[0];
    const float* Win  = (const float*)d_in[1];
    const float* bin  = (const float*)d_in[2];
    const float* Wout = (const float*)d_in[3];
    const float* bout = (const float*)d_in[4];
    const float* init = (const float*)d_in[5];
    const float* ap   = (const float*)d_in[6];
    float* out = (float*)d_out;

    cudaFuncSetAttribute((const void*)gemm_mma<__half>,
                         cudaFuncAttributeMaxDynamicSharedMemorySize, SMEM_TOTAL);
    cudaFuncSetAttribute((const void*)gemm_mma<float>,
                         cudaFuncAttributeMaxDynamicSharedMemorySize, SMEM_TOTAL);

    __half *xh, *yh, *xp, *w1, *w2;
    cudaGetSymbolAddress((void**)&xh, g_xh);
    cudaGetSymbolAddress((void**)&yh, g_yh);
    cudaGetSymbolAddress((void**)&xp, g_xp);
    cudaGetSymbolAddress((void**)&w1, g_w1);
    cudaGetSymbolAddress((void**)&w2, g_w2);

    convw_kernel<<<(2 * N4W + 255) / 256, 256>>>(Win, Wout, ap);
    int n4x = (MROWS * DIM) / 4;
    convx_kernel<<<(n4x + 255) / 256, 256>>>(x, xh, n4x);

    dim3 ggrid(DIM / BN, MROWS / BM);
    gemm_mma<__half><<<ggrid, 256, SMEM_TOTAL>>>(xh, w1, bin, xp);

    chunk_end_kernel<<<dim3(NCHUNK, BATCH), 256>>>(init);
    carry_kernel<<<dim3(2, BATCH), 256>>>(init);
    scan_kernel<<<dim3(NCHUNK, BATCH), 256>>>(init);

    gemm_mma<float><<<ggrid, 256, SMEM_TOTAL>>>(yh, w2, bout, out);
}